// round 1
// baseline (speedup 1.0000x reference)
#include <cuda_runtime.h>
#include <math.h>

#define B     128
#define H     1024
#define Z     256
#define SRC   64
#define KMAX  48
#define INDIM 1281          // Z + 1 + H
#define XLD   1312          // padded x leading dim (41*32, mult of 32 and 4)
#define BH    (B*H)
#define G4    4096

// out layout: z[B,K,Z] | mu | sigma | h_f[2,B,H] | c_f[2,B,H]
#define OUT_MU 1572864      // B*KMAX*Z
#define OUT_SG 3145728
#define OUT_H  4718592
#define OUT_C  4980736

// ---------------- device scratch (static, no allocs) ----------------
__device__ __align__(16) float g_h[2*BH];
__device__ __align__(16) float g_c[2*BH];
__device__ __align__(16) float g_x[B*XLD];
__device__ __align__(16) float g_wih0p[G4*XLD];   // W_ih0 padded to K=1312 (zero pad)
__device__ __align__(16) float g_gates[B*G4];
__device__ __align__(16) float g_h0n[BH];
__device__ __align__(16) float g_h1n[BH];
__device__ __align__(16) float g_mu[B*Z];
__device__ __align__(16) float g_sg[B*Z];
__device__ __align__(16) float g_qw[BH];
__device__ __align__(16) float g_wt[BH];

// ---------------- packed f32x2 helpers (sm_103a FFMA2) ----------------
__device__ __forceinline__ void dfma2(unsigned long long& d, unsigned long long a, unsigned long long b) {
    asm("fma.rn.f32x2 %0, %1, %2, %0;" : "+l"(d) : "l"(a), "l"(b));
}
__device__ __forceinline__ unsigned long long fpack(float x, float y) {
    unsigned long long r; asm("mov.b64 %0, {%1, %2};" : "=l"(r) : "f"(x), "f"(y)); return r;
}
__device__ __forceinline__ float2 funpack(unsigned long long v) {
    float2 r; asm("mov.b64 {%0, %1}, %2;" : "=f"(r.x), "=f"(r.y) : "l"(v)); return r;
}

// ---------------- generic 2-operand-pair GEMM ----------------
// C[m,n] = act( sum_k A1[m,k]W1[n,k] + sum_k A2[m,k]W2[n,k] + bias1[n] + bias2[n] )
// M = 128 (grid.y * MT), N = grid.x * NT, K1/K2 multiples of 32, lds multiples of 4.
template<int MT, int NT, int ACT>
__global__ __launch_bounds__(256) void gemm2k(
    const float* __restrict__ A1, int lda1, const float* __restrict__ W1, int ldw1, int K1,
    const float* __restrict__ A2, int lda2, const float* __restrict__ W2, int ldw2, int K2,
    const float* __restrict__ bias1, const float* __restrict__ bias2,
    float* __restrict__ C, int ldc)
{
    constexpr int RPT  = MT*NT/256;   // rows per thread
    constexpr int APL  = MT*32/256;   // A floats loaded per thread per chunk
    constexpr int WPL  = NT*32/256;
    constexpr int TPRA = 32/APL;
    constexpr int TPRW = 32/WPL;
    __shared__ __align__(16) float As[32][MT+4];  // k-major, padded stride
    __shared__ float Ws[NT][33];

    const int t  = threadIdx.x;
    const int n0 = blockIdx.x * NT, m0 = blockIdx.y * MT;
    const int tn = t % NT;
    const int tm = (t / NT) * RPT;
    const int lmA = t / TPRA, lkA = (t % TPRA) * APL;
    const int lnW = t / TPRW, lkW = (t % TPRW) * WPL;

    unsigned long long acc[RPT/2];
#pragma unroll
    for (int i = 0; i < RPT/2; i++) acc[i] = 0ull;  // bits(0,0)

    for (int pair = 0; pair < 2; pair++) {
        const float* A = pair ? A2 : A1;
        const float* W = pair ? W2 : W1;
        const int lda  = pair ? lda2 : lda1;
        const int ldw  = pair ? ldw2 : ldw1;
        const int K    = pair ? K2  : K1;
        if (K == 0) continue;
        const float* Arow = A + (size_t)(m0 + lmA) * lda + lkA;
        const float* Wrow = W + (size_t)(n0 + lnW) * ldw + lkW;

        for (int k0 = 0; k0 < K; k0 += 32) {
            float4 ab[APL/4], wb[WPL/4];
#pragma unroll
            for (int v = 0; v < APL/4; v++) ab[v] = *(const float4*)(Arow + k0 + 4*v);
#pragma unroll
            for (int v = 0; v < WPL/4; v++) wb[v] = *(const float4*)(Wrow + k0 + 4*v);
            __syncthreads();
#pragma unroll
            for (int v = 0; v < APL/4; v++) {
                As[lkA+4*v+0][lmA] = ab[v].x;
                As[lkA+4*v+1][lmA] = ab[v].y;
                As[lkA+4*v+2][lmA] = ab[v].z;
                As[lkA+4*v+3][lmA] = ab[v].w;
            }
#pragma unroll
            for (int v = 0; v < WPL/4; v++) {
                Ws[lnW][lkW+4*v+0] = wb[v].x;
                Ws[lnW][lkW+4*v+1] = wb[v].y;
                Ws[lnW][lkW+4*v+2] = wb[v].z;
                Ws[lnW][lkW+4*v+3] = wb[v].w;
            }
            __syncthreads();
#pragma unroll
            for (int kk = 0; kk < 32; kk++) {
                float w = Ws[tn][kk];
                unsigned long long bw = fpack(w, w);
#pragma unroll
                for (int v = 0; v < RPT/4; v++) {
                    float4 av = *(const float4*)(&As[kk][tm + 4*v]);
                    dfma2(acc[2*v+0], fpack(av.x, av.y), bw);
                    dfma2(acc[2*v+1], fpack(av.z, av.w), bw);
                }
            }
        }
    }

    float bb = 0.f;
    if (bias1) bb += bias1[n0 + tn];
    if (bias2) bb += bias2[n0 + tn];
#pragma unroll
    for (int i = 0; i < RPT/2; i++) {
        float2 v = funpack(acc[i]);
        float v0 = v.x + bb, v1 = v.y + bb;
        if (ACT == 1) { v0 = tanhf(v0); v1 = tanhf(v1); }
        C[(size_t)(m0 + tm + 2*i + 0) * ldc + n0 + tn] = v0;
        C[(size_t)(m0 + tm + 2*i + 1) * ldc + n0 + tn] = v1;
    }
}

// ---------------- small kernels ----------------
__global__ void prep_wih0(const float* __restrict__ W) {
    int idx = blockIdx.x * 256 + threadIdx.x;      // G4*XLD total
    int row = idx / XLD, kk = idx - row * XLD;
    g_wih0p[idx] = (kk < INDIM) ? W[(size_t)row * INDIM + kk] : 0.f;
}

__global__ void init_state(const float* __restrict__ h0, const float* __restrict__ c0) {
    int i = blockIdx.x * 256 + threadIdx.x;        // 2*BH total
    g_h[i] = h0[i];
    g_c[i] = c0[i];
}

__global__ void init_x(const float* __restrict__ z0, const int* __restrict__ kk) {
    int idx = blockIdx.x * 256 + threadIdx.x;      // B*XLD total
    if (idx >= B * XLD) return;
    int b = idx / XLD, col = idx - b * XLD;
    float v = 0.f;
    if (col < Z)       v = z0[b * Z + col];
    else if (col == Z) v = (float)kk[b];
    g_x[idx] = v;
}

__global__ void lstm_cell(float* __restrict__ hs, float* __restrict__ cs,
                          float* __restrict__ hn_out, const int* __restrict__ kk, float stepf) {
    int idx = blockIdx.x * 256 + threadIdx.x;      // BH total
    int b = idx >> 10, h = idx & (H - 1);
    const float* g = g_gates + (size_t)b * G4;
    float gi = g[h], gf = g[h + H], gg = g[h + 2*H], go = g[h + 3*H];
    float co = cs[idx], ho = hs[idx];
    float si = 1.f / (1.f + expf(-gi));
    float sf = 1.f / (1.f + expf(-gf));
    float so = 1.f / (1.f + expf(-go));
    float cn = sf * co + si * tanhf(gg);
    float hn = so * tanhf(cn);
    hn_out[idx] = hn;                              // unfrozen output for next layer / generator
    bool frozen = stepf >= (float)kk[b];
    hs[idx] = frozen ? ho : hn;
    cs[idx] = frozen ? co : cn;
}

__global__ void zstep(float* __restrict__ out, const float* __restrict__ eps,
                      const int* __restrict__ kk, int step) {
    int idx = blockIdx.x * 256 + threadIdx.x;      // B*Z total
    int b = idx >> 8, n = idx & (Z - 1);
    float m = g_mu[idx], s = g_sg[idx];
    float z = m + expf(s) * eps[(size_t)step * B * Z + idx];
    g_x[(size_t)b * XLD + n] = z;                  // unmasked z feeds next step
    int valid = step < kk[b];
    size_t o = (size_t)b * KMAX * Z + (size_t)step * Z + n;
    out[o]          = valid ? z : 0.f;
    out[OUT_MU + o] = valid ? m : 0.f;
    out[OUT_SG + o] = valid ? s : 0.f;
}

__global__ void attn_core(const float* __restrict__ ctx) {
    __shared__ float sq[H];
    __shared__ float sal[SRC];
    int b = blockIdx.x, t = threadIdx.x;
    for (int i = t; i < H; i += 256) sq[i] = g_qw[(size_t)b * H + i];
    __syncthreads();
    int warp = t >> 5, lane = t & 31;
#pragma unroll
    for (int s8 = 0; s8 < 8; s8++) {
        int s = warp * 8 + s8;
        const float* cr = ctx + ((size_t)b * SRC + s) * H;
        float a = 0.f;
        for (int k2 = lane; k2 < H; k2 += 32) a += cr[k2] * sq[k2];
#pragma unroll
        for (int o = 16; o > 0; o >>= 1) a += __shfl_xor_sync(0xffffffffu, a, o);
        if (lane == 0) sal[s] = a;
    }
    __syncthreads();
    if (warp == 0) {
        float v0 = sal[lane], v1 = sal[lane + 32];
        float mx = fmaxf(v0, v1);
#pragma unroll
        for (int o = 16; o > 0; o >>= 1) mx = fmaxf(mx, __shfl_xor_sync(0xffffffffu, mx, o));
        float e0 = expf(v0 - mx), e1 = expf(v1 - mx);
        float sm = e0 + e1;
#pragma unroll
        for (int o = 16; o > 0; o >>= 1) sm += __shfl_xor_sync(0xffffffffu, sm, o);
        float inv = 1.f / sm;
        sal[lane] = e0 * inv; sal[lane + 32] = e1 * inv;
    }
    __syncthreads();
    for (int h = t; h < H; h += 256) {
        float a = 0.f;
#pragma unroll 8
        for (int s = 0; s < SRC; s++) a += sal[s] * ctx[((size_t)b * SRC + s) * H + h];
        g_wt[(size_t)b * H + h] = a;
    }
}

__global__ void final_copy(float* __restrict__ out) {
    int i = blockIdx.x * 256 + threadIdx.x;        // 2*BH total
    out[OUT_H + i] = g_h[i];
    out[OUT_C + i] = g_c[i];
}

// ---------------- orchestration ----------------
extern "C" void kernel_launch(void* const* d_in, const int* in_sizes, int n_in,
                              void* d_out, int out_size) {
    const float* h0    = (const float*)d_in[0];
    const float* c0    = (const float*)d_in[1];
    const float* ctx   = (const float*)d_in[2];
    const float* z0    = (const float*)d_in[3];
    const int*   kin   = (const int*)  d_in[4];
    const float* eps   = (const float*)d_in[5];
    const float* W_ih0 = (const float*)d_in[6];
    const float* W_hh0 = (const float*)d_in[7];
    const float* b_ih0 = (const float*)d_in[8];
    const float* b_hh0 = (const float*)d_in[9];
    const float* W_ih1 = (const float*)d_in[10];
    const float* W_hh1 = (const float*)d_in[11];
    const float* b_ih1 = (const float*)d_in[12];
    const float* b_hh1 = (const float*)d_in[13];
    const float* aWin  = (const float*)d_in[14];
    const float* aWout = (const float*)d_in[15];
    const float* mu_W  = (const float*)d_in[16];
    const float* mu_b  = (const float*)d_in[17];
    const float* sg_W  = (const float*)d_in[18];
    const float* sg_b  = (const float*)d_in[19];
    float* out = (float*)d_out;

    float *p_h, *p_c, *p_x, *p_wp, *p_gates, *p_h0n, *p_h1n, *p_mu, *p_sg, *p_qw, *p_wt;
    cudaGetSymbolAddress((void**)&p_h,     g_h);
    cudaGetSymbolAddress((void**)&p_c,     g_c);
    cudaGetSymbolAddress((void**)&p_x,     g_x);
    cudaGetSymbolAddress((void**)&p_wp,    g_wih0p);
    cudaGetSymbolAddress((void**)&p_gates, g_gates);
    cudaGetSymbolAddress((void**)&p_h0n,   g_h0n);
    cudaGetSymbolAddress((void**)&p_h1n,   g_h1n);
    cudaGetSymbolAddress((void**)&p_mu,    g_mu);
    cudaGetSymbolAddress((void**)&p_sg,    g_sg);
    cudaGetSymbolAddress((void**)&p_qw,    g_qw);
    cudaGetSymbolAddress((void**)&p_wt,    g_wt);

    // --- init ---
    prep_wih0<<<(G4 * XLD) / 256, 256>>>(W_ih0);
    init_state<<<(2 * BH) / 256, 256>>>(h0, c0);
    init_x<<<(B * XLD + 255) / 256, 256>>>(z0, kin);

    // attn0 from c0 layer 1
    gemm2k<64,32,0><<<dim3(H/32, 2), 256>>>(c0 + BH, H, aWin, H, H,
                                            nullptr, 0, nullptr, 0, 0,
                                            nullptr, nullptr, p_qw, H);
    attn_core<<<B, 256>>>(ctx);
    gemm2k<64,32,1><<<dim3(H/32, 2), 256>>>(p_wt, H, aWout, 2*H, H,
                                            c0 + BH, H, aWout + H, 2*H, H,
                                            nullptr, nullptr, p_x + Z + 1, XLD);

    // --- recurrent loop ---
    for (int step = 0; step < KMAX; step++) {
        // layer 0 gates: x @ W_ih0^T + h0 @ W_hh0^T + biases
        gemm2k<64,64,0><<<dim3(G4/64, 2), 256>>>(p_x, XLD, p_wp, XLD, XLD,
                                                 p_h, H, W_hh0, H, H,
                                                 b_ih0, b_hh0, p_gates, G4);
        lstm_cell<<<BH/256, 256>>>(p_h, p_c, p_h0n, kin, (float)step);

        // layer 1 gates: h0n @ W_ih1^T + h1 @ W_hh1^T + biases
        gemm2k<64,64,0><<<dim3(G4/64, 2), 256>>>(p_h0n, H, W_ih1, H, H,
                                                 p_h + BH, H, W_hh1, H, H,
                                                 b_ih1, b_hh1, p_gates, G4);
        lstm_cell<<<BH/256, 256>>>(p_h + BH, p_c + BH, p_h1n, kin, (float)step);

        // generator
        gemm2k<64,32,0><<<dim3(Z/32, 2), 256>>>(p_h1n, H, mu_W, H, H,
                                                nullptr, 0, nullptr, 0, 0,
                                                mu_b, nullptr, p_mu, Z);
        gemm2k<64,32,0><<<dim3(Z/32, 2), 256>>>(p_h1n, H, sg_W, H, H,
                                                nullptr, 0, nullptr, 0, 0,
                                                sg_b, nullptr, p_sg, Z);
        zstep<<<(B*Z)/256, 256>>>(out, eps, kin, step);

        // attention for next step (from unfrozen output h1n)
        gemm2k<64,32,0><<<dim3(H/32, 2), 256>>>(p_h1n, H, aWin, H, H,
                                                nullptr, 0, nullptr, 0, 0,
                                                nullptr, nullptr, p_qw, H);
        attn_core<<<B, 256>>>(ctx);
        gemm2k<64,32,1><<<dim3(H/32, 2), 256>>>(p_wt, H, aWout, 2*H, H,
                                                p_h1n, H, aWout + H, 2*H, H,
                                                nullptr, nullptr, p_x + Z + 1, XLD);
    }

    final_copy<<<(2 * BH) / 256, 256>>>(out);
    (void)in_sizes; (void)n_in; (void)out_size;
}

// round 2
// speedup vs baseline: 2.3278x; 2.3278x over previous
#include <cuda_runtime.h>
#include <math.h>

#define B     128
#define H     1024
#define Z     256
#define SRC   64
#define KMAX  48
#define BH    (B*H)
#define X0LD  2336          // [z(256) | k(1) | attn(1024) | pad(31) | h0(1024)]
#define X1LD  2048          // [h0n | h1]
#define G4    4096
#define KS_GATE 4
#define KS_GEN  12
#define KS_OUT  16

// out layout: z[B,K,Z] | mu | sigma | h_f[2,B,H] | c_f[2,B,H]
#define OUT_MU 1572864
#define OUT_SG 3145728
#define OUT_H  4718592
#define OUT_C  4980736

// ---------------- device scratch ----------------
__device__ __align__(16) float g_x0[B*X0LD];
__device__ __align__(16) float g_x1[B*X1LD];
__device__ __align__(16) float g_xa[B*X1LD];      // [weighted | q]
__device__ __align__(16) float g_c[2*BH];
__device__ __align__(16) float g_w0[G4*X0LD];     // [W_ih0 | 0pad | W_hh0]
__device__ __align__(16) float g_w1[G4*X1LD];     // [W_ih1 | W_hh1]
__device__ __align__(16) float g_wg[1536*H];      // [mu_W ; sigma_W ; attn_W_in]
__device__ __align__(16) float g_part[16*B*G4];   // split-K partials

// ---------------- packed f32x2 (sm_103a FFMA2) ----------------
__device__ __forceinline__ void dfma2(unsigned long long& d, unsigned long long a, unsigned long long b){
    asm("fma.rn.f32x2 %0, %1, %2, %0;" : "+l"(d) : "l"(a), "l"(b));
}
__device__ __forceinline__ unsigned long long fpack(float x, float y){
    unsigned long long r; asm("mov.b64 %0, {%1,%2};" : "=l"(r) : "f"(x), "f"(y)); return r;
}
__device__ __forceinline__ float2 funpack(unsigned long long v){
    float2 r; asm("mov.b64 {%0,%1}, %2;" : "=f"(r.x), "=f"(r.y) : "l"(v)); return r;
}
__device__ __forceinline__ float sigm(float x){ return 1.f/(1.f+expf(-x)); }

// ---------------- 128x128-tile split-K GEMM, 8x8 thread tile ----------------
// C_partial[z][m][n] += sum over this block's K-units of A[m,k]*W[n,k]
// grid = (N/128, KS). K multiple of 32. Partials to g_part[(z*128+m)*4096 + n].
__global__ __launch_bounds__(256) void gemm128(
    const float* __restrict__ A, int lda,
    const float* __restrict__ W, int ldw, int K)
{
    __shared__ __align__(16) float As[16][128];
    __shared__ __align__(16) float Ws[16][128];
    const int t  = threadIdx.x;
    const int n0 = blockIdx.x << 7;
    const int z  = blockIdx.y, KS = gridDim.y;
    const int NU = K >> 5;                 // 32-wide k-units
    const int tm = (t >> 4) << 3;
    const int tn = (t & 15) << 3;
    const int lr = t >> 1;                 // loader row (m or n), 0..127
    const int lk = (t & 1) << 3;           // loader k offset within 16-chunk

    const float* Aptr = A + (size_t)lr * lda + lk;
    const float* Wptr = W + (size_t)(n0 + lr) * ldw + lk;

    unsigned long long acc[8][4];
#pragma unroll
    for (int i=0;i<8;i++)
#pragma unroll
        for (int j=0;j<4;j++) acc[i][j]=0ull;

    int cu = z, ch = 0;
    float4 a0r, a1r, w0r, w1r;
    {
        int ko = (cu<<5) + (ch<<4);
        a0r = *(const float4*)(Aptr + ko);
        a1r = *(const float4*)(Aptr + ko + 4);
        w0r = *(const float4*)(Wptr + ko);
        w1r = *(const float4*)(Wptr + ko + 4);
    }
    while (true) {
        __syncthreads();
        As[lk+0][lr]=a0r.x; As[lk+1][lr]=a0r.y; As[lk+2][lr]=a0r.z; As[lk+3][lr]=a0r.w;
        As[lk+4][lr]=a1r.x; As[lk+5][lr]=a1r.y; As[lk+6][lr]=a1r.z; As[lk+7][lr]=a1r.w;
        Ws[lk+0][lr]=w0r.x; Ws[lk+1][lr]=w0r.y; Ws[lk+2][lr]=w0r.z; Ws[lk+3][lr]=w0r.w;
        Ws[lk+4][lr]=w1r.x; Ws[lk+5][lr]=w1r.y; Ws[lk+6][lr]=w1r.z; Ws[lk+7][lr]=w1r.w;
        __syncthreads();
        int nu = cu, nh = ch ^ 1;
        if (nh == 0) nu += KS;
        bool hasNext = (nu < NU);
        if (hasNext) {                     // prefetch next chunk during compute
            int ko = (nu<<5) + (nh<<4);
            a0r = *(const float4*)(Aptr + ko);
            a1r = *(const float4*)(Aptr + ko + 4);
            w0r = *(const float4*)(Wptr + ko);
            w1r = *(const float4*)(Wptr + ko + 4);
        }
#pragma unroll
        for (int kk=0; kk<16; kk++) {
            float4 av0 = *(const float4*)&As[kk][tm];
            float4 av1 = *(const float4*)&As[kk][tm+4];
            float4 wv0 = *(const float4*)&Ws[kk][tn];
            float4 wv1 = *(const float4*)&Ws[kk][tn+4];
            unsigned long long wp0 = fpack(wv0.x, wv0.y);
            unsigned long long wp1 = fpack(wv0.z, wv0.w);
            unsigned long long wp2 = fpack(wv1.x, wv1.y);
            unsigned long long wp3 = fpack(wv1.z, wv1.w);
            float am[8] = {av0.x,av0.y,av0.z,av0.w,av1.x,av1.y,av1.z,av1.w};
#pragma unroll
            for (int mi=0; mi<8; mi++) {
                unsigned long long ap = fpack(am[mi], am[mi]);
                dfma2(acc[mi][0], ap, wp0);
                dfma2(acc[mi][1], ap, wp1);
                dfma2(acc[mi][2], ap, wp2);
                dfma2(acc[mi][3], ap, wp3);
            }
        }
        if (!hasNext) break;
        cu = nu; ch = nh;
    }
    float* P = g_part + ((size_t)(z*128 + tm))*4096 + n0 + tn;
#pragma unroll
    for (int mi=0; mi<8; mi++) {
        float2 c0v = funpack(acc[mi][0]);
        float2 c1v = funpack(acc[mi][1]);
        float2 c2v = funpack(acc[mi][2]);
        float2 c3v = funpack(acc[mi][3]);
        *(float4*)(P + (size_t)mi*4096)     = make_float4(c0v.x,c0v.y,c1v.x,c1v.y);
        *(float4*)(P + (size_t)mi*4096 + 4) = make_float4(c2v.x,c2v.y,c3v.x,c3v.y);
    }
}

// ---------------- fused epilogues ----------------
__global__ void lstm_red(float* __restrict__ hst, int ldh, float* __restrict__ cst,
                         float* __restrict__ hout, int ldo,
                         const float* __restrict__ bi, const float* __restrict__ bh,
                         const int* __restrict__ kin, int step)
{
    int i = blockIdx.x*256 + threadIdx.x;          // BH
    int b = i >> 10, hh = i & 1023;
    float g[4];
#pragma unroll
    for (int gi=0; gi<4; gi++) {
        int col = (gi<<10) + hh;
        float s = bi[col] + bh[col];
#pragma unroll
        for (int zz=0; zz<KS_GATE; zz++)
            s += g_part[((size_t)(zz*128+b))*4096 + col];
        g[gi] = s;
    }
    float* hp = hst + (size_t)b*ldh + hh;
    float ho = *hp, co = cst[i];
    float cn = sigm(g[1])*co + sigm(g[0])*tanhf(g[2]);
    float hn = sigm(g[3])*tanhf(cn);
    hout[(size_t)b*ldo + hh] = hn;                 // unfrozen output
    bool frozen = step >= kin[b];
    *hp    = frozen ? ho : hn;
    cst[i] = frozen ? co : cn;
}

__global__ void zstep_red(float* __restrict__ out, const float* __restrict__ eps,
                          const float* __restrict__ mub, const float* __restrict__ sgb,
                          const int* __restrict__ kin, int step)
{
    int i = blockIdx.x*256 + threadIdx.x;          // B*Z
    int b = i >> 8, zi = i & 255;
    float m = mub[zi], s = sgb[zi];
#pragma unroll
    for (int zz=0; zz<KS_GEN; zz++) {
        const float* p = g_part + ((size_t)(zz*128+b))*4096;
        m += p[zi];
        s += p[256+zi];
    }
    float zval = m + expf(s) * eps[((size_t)step*B + b)*Z + zi];
    g_x0[(size_t)b*X0LD + zi] = zval;              // unmasked z feeds next step
    bool valid = step < kin[b];
    size_t o = ((size_t)b*KMAX + step)*Z + zi;
    out[o]          = valid ? zval : 0.f;
    out[OUT_MU + o] = valid ? m : 0.f;
    out[OUT_SG + o] = valid ? s : 0.f;
}

__global__ void attn_core(const float* __restrict__ ctx)
{
    __shared__ float sq[H];
    __shared__ float sal[SRC];
    int b = blockIdx.x, t = threadIdx.x;
    for (int i=t; i<H; i+=256) {                   // reduce qw from gen partials (cols 512..1535)
        float s = 0.f;
#pragma unroll
        for (int zz=0; zz<KS_GEN; zz++)
            s += g_part[((size_t)(zz*128+b))*4096 + 512 + i];
        sq[i] = s;
    }
    __syncthreads();
    int warp = t>>5, lane = t&31;
#pragma unroll
    for (int s8=0; s8<8; s8++) {
        int s = warp*8 + s8;
        const float* cr = ctx + ((size_t)b*SRC + s)*H;
        float a = 0.f;
        for (int k2=lane; k2<H; k2+=32) a += cr[k2]*sq[k2];
#pragma unroll
        for (int o=16;o>0;o>>=1) a += __shfl_xor_sync(0xffffffffu, a, o);
        if (lane==0) sal[s] = a;
    }
    __syncthreads();
    if (warp==0) {
        float v0 = sal[lane], v1 = sal[lane+32];
        float mx = fmaxf(v0,v1);
#pragma unroll
        for (int o=16;o>0;o>>=1) mx = fmaxf(mx, __shfl_xor_sync(0xffffffffu,mx,o));
        float e0=expf(v0-mx), e1=expf(v1-mx);
        float sm=e0+e1;
#pragma unroll
        for (int o=16;o>0;o>>=1) sm += __shfl_xor_sync(0xffffffffu,sm,o);
        float inv=1.f/sm;
        sal[lane]=e0*inv; sal[lane+32]=e1*inv;
    }
    __syncthreads();
    for (int hh=t; hh<H; hh+=256) {
        float a=0.f;
#pragma unroll 8
        for (int s=0;s<SRC;s++) a += sal[s]*ctx[((size_t)b*SRC+s)*H + hh];
        g_xa[(size_t)b*X1LD + hh] = a;             // weighted -> left half of attn concat
    }
}

__global__ void attnout_red()
{
    int i = blockIdx.x*256 + threadIdx.x;          // BH
    int b = i>>10, hh = i&1023;
    float s = 0.f;
#pragma unroll
    for (int zz=0; zz<KS_OUT; zz++)
        s += g_part[((size_t)(zz*128+b))*4096 + hh];
    g_x0[(size_t)b*X0LD + 257 + hh] = tanhf(s);
}

// ---------------- prep / init / final ----------------
__global__ void prep_w0(const float* __restrict__ Wih, const float* __restrict__ Whh){
    int i = blockIdx.x*256 + threadIdx.x;
    int r = i / X0LD, c = i - r*X0LD;
    float v;
    if (c < 1281)      v = Wih[(size_t)r*1281 + c];
    else if (c < 1312) v = 0.f;
    else               v = Whh[(size_t)r*1024 + (c-1312)];
    g_w0[i] = v;
}
__global__ void prep_w1(const float* __restrict__ Wih, const float* __restrict__ Whh){
    int i = blockIdx.x*256 + threadIdx.x;
    int r = i >> 11, c = i & 2047;
    g_w1[i] = (c < 1024) ? Wih[(size_t)r*1024 + c] : Whh[(size_t)r*1024 + (c-1024)];
}
__global__ void prep_wg(const float* __restrict__ muW, const float* __restrict__ sgW,
                        const float* __restrict__ aWin){
    int i = blockIdx.x*256 + threadIdx.x;
    int r = i >> 10, c = i & 1023;
    float v;
    if (r < 256)      v = muW[(size_t)r*1024 + c];
    else if (r < 512) v = sgW[(size_t)(r-256)*1024 + c];
    else              v = aWin[(size_t)(r-512)*1024 + c];
    g_wg[i] = v;
}
__global__ void init_a(const float* __restrict__ z0, const int* __restrict__ kin,
                       const float* __restrict__ h0){
    int i = blockIdx.x*256 + threadIdx.x;          // B*X0LD
    int b = i / X0LD, c = i - b*X0LD;
    float v = 0.f;
    if (c < 256)        v = z0[(b<<8) + c];
    else if (c == 256)  v = (float)kin[b];
    else if (c >= 1312) v = h0[(b<<10) + (c-1312)];
    g_x0[i] = v;
}
__global__ void init_b(const float* __restrict__ h0, const float* __restrict__ c0){
    int i = blockIdx.x*256 + threadIdx.x;          // B*X1LD = 2*BH
    int b = i >> 11, c = i & 2047;
    g_x1[i] = (c < 1024) ? 0.f : h0[BH + (b<<10) + (c-1024)];
    g_xa[i] = (c < 1024) ? 0.f : c0[BH + (b<<10) + (c-1024)];   // q = c0[-1] for attn0
    g_c[i]  = c0[i];
}
__global__ void final_copy(float* __restrict__ out){
    int i = blockIdx.x*256 + threadIdx.x;          // BH
    int b = i>>10, hh = i&1023;
    out[OUT_H + i]      = g_x0[(size_t)b*X0LD + 1312 + hh];
    out[OUT_H + BH + i] = g_x1[(size_t)b*X1LD + 1024 + hh];
    out[OUT_C + i]      = g_c[i];
    out[OUT_C + BH + i] = g_c[BH + i];
}

// ---------------- orchestration ----------------
extern "C" void kernel_launch(void* const* d_in, const int* in_sizes, int n_in,
                              void* d_out, int out_size) {
    const float* h0    = (const float*)d_in[0];
    const float* c0    = (const float*)d_in[1];
    const float* ctx   = (const float*)d_in[2];
    const float* z0    = (const float*)d_in[3];
    const int*   kin   = (const int*)  d_in[4];
    const float* eps   = (const float*)d_in[5];
    const float* W_ih0 = (const float*)d_in[6];
    const float* W_hh0 = (const float*)d_in[7];
    const float* b_ih0 = (const float*)d_in[8];
    const float* b_hh0 = (const float*)d_in[9];
    const float* W_ih1 = (const float*)d_in[10];
    const float* W_hh1 = (const float*)d_in[11];
    const float* b_ih1 = (const float*)d_in[12];
    const float* b_hh1 = (const float*)d_in[13];
    const float* aWin  = (const float*)d_in[14];
    const float* aWout = (const float*)d_in[15];
    const float* mu_W  = (const float*)d_in[16];
    const float* mu_b  = (const float*)d_in[17];
    const float* sg_W  = (const float*)d_in[18];
    const float* sg_b  = (const float*)d_in[19];
    float* out = (float*)d_out;

    float *p_x0, *p_x1, *p_xa, *p_c, *p_w0, *p_w1, *p_wg;
    cudaGetSymbolAddress((void**)&p_x0, g_x0);
    cudaGetSymbolAddress((void**)&p_x1, g_x1);
    cudaGetSymbolAddress((void**)&p_xa, g_xa);
    cudaGetSymbolAddress((void**)&p_c,  g_c);
    cudaGetSymbolAddress((void**)&p_w0, g_w0);
    cudaGetSymbolAddress((void**)&p_w1, g_w1);
    cudaGetSymbolAddress((void**)&p_wg, g_wg);

    // weight concat + state init
    prep_w0<<<(G4*X0LD)/256, 256>>>(W_ih0, W_hh0);
    prep_w1<<<(G4*X1LD)/256, 256>>>(W_ih1, W_hh1);
    prep_wg<<<(1536*H)/256, 256>>>(mu_W, sg_W, aWin);
    init_a<<<(B*X0LD)/256, 256>>>(z0, kin, h0);
    init_b<<<(B*X1LD)/256, 256>>>(h0, c0);

    // attn0: q = c0[-1]
    gemm128<<<dim3(12, KS_GEN), 256>>>(c0 + BH, H, p_wg, H, H);
    attn_core<<<B, 256>>>(ctx);
    gemm128<<<dim3(8, KS_OUT), 256>>>(p_xa, X1LD, aWout, 2*H, 2*H);
    attnout_red<<<BH/256, 256>>>();

    for (int step = 0; step < KMAX; step++) {
        gemm128<<<dim3(32, KS_GATE), 256>>>(p_x0, X0LD, p_w0, X0LD, X0LD);
        lstm_red<<<BH/256, 256>>>(p_x0 + 1312, X0LD, p_c, p_x1, X1LD, b_ih0, b_hh0, kin, step);
        gemm128<<<dim3(32, KS_GATE), 256>>>(p_x1, X1LD, p_w1, X1LD, X1LD);
        lstm_red<<<BH/256, 256>>>(p_x1 + 1024, X1LD, p_c + BH, p_xa + 1024, X1LD, b_ih1, b_hh1, kin, step);
        gemm128<<<dim3(12, KS_GEN), 256>>>(p_xa + 1024, X1LD, p_wg, H, H);
        zstep_red<<<(B*Z)/256, 256>>>(out, eps, mu_b, sg_b, kin, step);
        attn_core<<<B, 256>>>(ctx);
        gemm128<<<dim3(8, KS_OUT), 256>>>(p_xa, X1LD, aWout, 2*H, 2*H);
        attnout_red<<<BH/256, 256>>>();
    }

    final_copy<<<BH/256, 256>>>(out);
    (void)in_sizes; (void)n_in; (void)out_size;
}